// round 3
// baseline (speedup 1.0000x reference)
#include <cuda_runtime.h>
#include <cuda_bf16.h>
#include <math.h>

// Problem constants
#define BW    512
#define LQ    256          // window length (Wd*Wh*Ww = 4*64)
#define C     128
#define H     4
#define HD    32
#define M_TAB 1575         // (2*8-1)*(2*8-1)*(2*4-1)
#define ROWS_TOT (BW*LQ)   // 131072

// Device-global scratch (allocation-free requirement)
__device__ float g_Q[BW*H*LQ*HD];
__device__ float g_K[BW*H*LQ*HD];
__device__ float g_V[BW*H*LQ*HD];
__device__ float g_O[BW*LQ*C];
__device__ float g_bias16[M_TAB*H];
__device__ float g_biasT[H*LQ*LQ];   // [h][k][q]  (transposed for coalesced attn reads)

// ---------------------------------------------------------------------------
// 1) CPB MLP: bias16[m][h] = 16*sigmoid( relu(table[m]@w1^T + b1) @ w2[h] )
// ---------------------------------------------------------------------------
__global__ void k_cpb(const float* __restrict__ rel_table,
                      const float* __restrict__ w1,
                      const float* __restrict__ b1,
                      const float* __restrict__ w2)
{
    int i = blockIdx.x * blockDim.x + threadIdx.x;   // i = m*H + h
    if (i >= M_TAB * H) return;
    int m = i >> 2, h = i & 3;
    float t0 = rel_table[m*3+0], t1 = rel_table[m*3+1], t2 = rel_table[m*3+2];
    float acc = 0.f;
    for (int j = 0; j < 512; j++) {
        float hv = fmaf(t0, w1[j*3+0], fmaf(t1, w1[j*3+1], fmaf(t2, w1[j*3+2], b1[j])));
        hv = fmaxf(hv, 0.f);
        acc = fmaf(hv, w2[h*512+j], acc);
    }
    g_bias16[i] = 16.f / (1.f + __expf(-acc));
}

// ---------------------------------------------------------------------------
// 2) Expand (transposed): biasT[h][k][q] = bias16[rel_index[q*L+k]][h]
// ---------------------------------------------------------------------------
__global__ void k_expand(const int* __restrict__ rel_index)
{
    int i = blockIdx.x * blockDim.x + threadIdx.x;   // h<<16 | k<<8 | q
    if (i >= H*LQ*LQ) return;
    int h = i >> 16;
    int k = (i >> 8) & 255;
    int q = i & 255;
    g_biasT[i] = g_bias16[rel_index[q*LQ + k]*H + h];
}

// ---------------------------------------------------------------------------
// 3) Fused QKV GEMM + bias + cosine-normalize q,k.
//    Block = 32 rows; 384 threads, thread c owns output column c.
// ---------------------------------------------------------------------------
__global__ void __launch_bounds__(384) k_qkv(const float* __restrict__ x,
                                             const float* __restrict__ qkv_w,
                                             const float* __restrict__ q_bias,
                                             const float* __restrict__ v_bias)
{
    __shared__ float xs[32][128];
    const int blk = blockIdx.x;           // 4096 blocks
    const long base = (long)blk * 32 * 128;
    const int tid = threadIdx.x;

    for (int i = tid; i < 32*128; i += 384) ((float*)xs)[i] = x[base + i];
    __syncthreads();

    const int c = tid;                    // 0..383
    const float4* w4 = (const float4*)(qkv_w + c * 128);
    float acc[32];
    #pragma unroll
    for (int r = 0; r < 32; r++) acc[r] = 0.f;

    for (int kk = 0; kk < 32; kk++) {
        float4 w = w4[kk];
        #pragma unroll
        for (int r = 0; r < 32; r++) {
            float4 xv = ((const float4*)xs[r])[kk];
            acc[r] = fmaf(xv.x, w.x, fmaf(xv.y, w.y, fmaf(xv.z, w.z, fmaf(xv.w, w.w, acc[r]))));
        }
    }

    const int rowbase = blk * 32;
    if (c < 256) {
        const bool isq = (c < 128);
        const int cc = isq ? c : (c - 128);
        const int h = cc >> 5, d = cc & 31;
        const float bias = isq ? q_bias[c] : 0.f;
        float* dst = isq ? g_Q : g_K;
        #pragma unroll 4
        for (int r = 0; r < 32; r++) {
            float v = acc[r] + bias;
            float ss = v * v;
            #pragma unroll
            for (int off = 16; off; off >>= 1)
                ss += __shfl_xor_sync(0xffffffffu, ss, off);
            float inv = 1.f / fmaxf(sqrtf(ss), 1e-12f);
            int g = rowbase + r;
            int b = g >> 8, l = g & 255;
            dst[(((b*H + h)*LQ + l) << 5) + d] = v * inv;
        }
    } else {
        const int cc = c - 256;
        const int h = cc >> 5, d = cc & 31;
        const float bias = v_bias[cc];
        #pragma unroll 4
        for (int r = 0; r < 32; r++) {
            int g = rowbase + r;
            int b = g >> 8, l = g & 255;
            g_V[(((b*H + h)*LQ + l) << 5) + d] = acc[r] + bias;
        }
    }
}

// ---------------------------------------------------------------------------
// 4) Attention: block = (b,h); 256 threads, thread = query row.
//    K,V tiles (64 KB) in dynamic smem.
//    Softmax with PROVABLY-SAFE FIXED MAX:
//      s = scale*(qn.kn) + bias, qn.kn in [-1,1], scale<=100, bias in (0,16)
//      => s <= scale+16. Diagonal has qn.kn=1 so max_k s >= scale,
//      hence sum_k exp(s - (scale+16)) >= e^-16: no under/overflow.
//    Removes per-k max/rescale chain (~33% fewer FMA, no serial dep).
// ---------------------------------------------------------------------------
__global__ void __launch_bounds__(256) k_attn(const float* __restrict__ logit_scale)
{
    extern __shared__ float sm[];
    float* ksm = sm;            // 256*32
    float* vsm = sm + 8192;     // 256*32

    const int bh = blockIdx.x;            // b*H + h
    const int h = bh & 3;
    const long base = (long)bh * (LQ * HD);
    const int tid = threadIdx.x;

    for (int i = tid; i < LQ*HD; i += 256) {
        ksm[i] = g_K[base + i];
        vsm[i] = g_V[base + i];
    }
    __syncthreads();

    const float scale = __expf(fminf(logit_scale[h], 4.6051702f)); // ln(100)
    const float fixmax = scale + 16.0f;

    float qv[32];
    {
        const float4* qp = (const float4*)(g_Q + base + (long)tid * HD);
        #pragma unroll
        for (int j = 0; j < 8; j++) {
            float4 t = qp[j];
            qv[4*j+0] = t.x; qv[4*j+1] = t.y; qv[4*j+2] = t.z; qv[4*j+3] = t.w;
        }
    }

    // biasT layout [h][k][q]: warp reads consecutive q at fixed k -> coalesced
    const float* biasT = g_biasT + (h << 16) + tid;

    float lsum = 0.f;
    float acc[32];
    #pragma unroll
    for (int d = 0; d < 32; d++) acc[d] = 0.f;

    for (int k = 0; k < LQ; k++) {
        const float4* kr = (const float4*)(ksm + k * HD);
        float s = 0.f;
        #pragma unroll
        for (int j = 0; j < 8; j++) {
            float4 t = kr[j];
            s = fmaf(qv[4*j+0], t.x, s);
            s = fmaf(qv[4*j+1], t.y, s);
            s = fmaf(qv[4*j+2], t.z, s);
            s = fmaf(qv[4*j+3], t.w, s);
        }
        s = fmaf(s, scale, biasT[k << 8]);

        float p = __expf(s - fixmax);
        lsum += p;
        const float4* vr = (const float4*)(vsm + k * HD);
        #pragma unroll
        for (int j = 0; j < 8; j++) {
            float4 t = vr[j];
            acc[4*j+0] = fmaf(p, t.x, acc[4*j+0]);
            acc[4*j+1] = fmaf(p, t.y, acc[4*j+1]);
            acc[4*j+2] = fmaf(p, t.z, acc[4*j+2]);
            acc[4*j+3] = fmaf(p, t.w, acc[4*j+3]);
        }
    }

    const float invl = 1.f / lsum;
    const int b = bh >> 2;
    float4* op = (float4*)(g_O + ((long)(b*LQ + tid) * C) + h * HD);
    #pragma unroll
    for (int j = 0; j < 8; j++) {
        float4 t;
        t.x = acc[4*j+0]*invl; t.y = acc[4*j+1]*invl;
        t.z = acc[4*j+2]*invl; t.w = acc[4*j+3]*invl;
        op[j] = t;
    }
}

// ---------------------------------------------------------------------------
// 5) Output projection: y = O @ proj_w^T + proj_b
// ---------------------------------------------------------------------------
__global__ void __launch_bounds__(128) k_proj(const float* __restrict__ proj_w,
                                              const float* __restrict__ proj_b,
                                              float* __restrict__ out)
{
    __shared__ float xs[32][128];
    const int blk = blockIdx.x;            // 4096 blocks of 32 rows
    const long base = (long)blk * 32 * 128;
    const int tid = threadIdx.x;

    for (int i = tid; i < 32*128; i += 128) ((float*)xs)[i] = g_O[base + i];
    __syncthreads();

    const float4* w4 = (const float4*)(proj_w + tid * 128);
    float acc[32];
    #pragma unroll
    for (int r = 0; r < 32; r++) acc[r] = 0.f;

    for (int kk = 0; kk < 32; kk++) {
        float4 w = w4[kk];
        #pragma unroll
        for (int r = 0; r < 32; r++) {
            float4 xv = ((const float4*)xs[r])[kk];
            acc[r] = fmaf(xv.x, w.x, fmaf(xv.y, w.y, fmaf(xv.z, w.z, fmaf(xv.w, w.w, acc[r]))));
        }
    }

    const float pb = proj_b[tid];
    #pragma unroll 4
    for (int r = 0; r < 32; r++)
        out[base + r * 128 + tid] = acc[r] + pb;
}

// ---------------------------------------------------------------------------
extern "C" void kernel_launch(void* const* d_in, const int* in_sizes, int n_in,
                              void* d_out, int out_size)
{
    const float* x           = (const float*)d_in[0];
    const float* qkv_w       = (const float*)d_in[1];
    const float* q_bias      = (const float*)d_in[2];
    const float* v_bias      = (const float*)d_in[3];
    const float* logit_scale = (const float*)d_in[4];
    const float* cpb_w1      = (const float*)d_in[5];
    const float* cpb_b1      = (const float*)d_in[6];
    const float* cpb_w2      = (const float*)d_in[7];
    const float* proj_w      = (const float*)d_in[8];
    const float* proj_b      = (const float*)d_in[9];
    const float* rel_table   = (const float*)d_in[10];
    const int*   rel_index   = (const int*)d_in[11];
    float* out = (float*)d_out;

    // Unconditional (no static guards); cudaFuncSetAttribute is not a stream
    // op and is graph-capture-safe.
    cudaFuncSetAttribute(k_attn, cudaFuncAttributeMaxDynamicSharedMemorySize, 64 * 1024);

    k_cpb<<<(M_TAB*H + 127) / 128, 128>>>(rel_table, cpb_w1, cpb_b1, cpb_w2);
    k_expand<<<(H*LQ*LQ) / 256, 256>>>(rel_index);
    k_qkv<<<ROWS_TOT / 32, 384>>>(x, qkv_w, q_bias, v_bias);
    k_attn<<<BW * H, 256, 64 * 1024>>>(logit_scale);
    k_proj<<<ROWS_TOT / 32, 128>>>(proj_w, proj_b, out);
}

// round 6
// speedup vs baseline: 1.2034x; 1.2034x over previous
#include <cuda_runtime.h>
#include <cuda_bf16.h>
#include <math.h>

// Problem constants
#define BW    512
#define LQ    256          // window length (Wd*Wh*Ww = 4*64)
#define C     128
#define H     4
#define HD    32
#define M_TAB 1575         // (2*8-1)*(2*8-1)*(2*4-1)
#define ROWS_TOT (BW*LQ)   // 131072

// Device-global scratch (allocation-free requirement)
__device__ float g_Q[BW*H*LQ*HD];
__device__ float g_K[BW*H*LQ*HD];
__device__ float g_V[BW*H*LQ*HD];
__device__ float g_O[BW*LQ*C];
__device__ float g_bias16[M_TAB*H];
__device__ float g_biasT[H*LQ*LQ];   // [h][k][q]  (coalesced attn reads)

// ---------------------------------------------------------------------------
// 1) CPB MLP, block per m: hidden shared across the 4 heads, j-parallel.
// ---------------------------------------------------------------------------
__global__ void __launch_bounds__(128) k_cpb(const float* __restrict__ rel_table,
                                             const float* __restrict__ w1,
                                             const float* __restrict__ b1,
                                             const float* __restrict__ w2)
{
    const int m = blockIdx.x;
    const int tid = threadIdx.x;
    const float t0 = rel_table[m*3+0], t1 = rel_table[m*3+1], t2 = rel_table[m*3+2];

    float a0 = 0.f, a1 = 0.f, a2 = 0.f, a3 = 0.f;
    for (int j = tid; j < 512; j += 128) {
        float hv = fmaf(t0, w1[j*3+0], fmaf(t1, w1[j*3+1], fmaf(t2, w1[j*3+2], b1[j])));
        hv = fmaxf(hv, 0.f);
        a0 = fmaf(hv, w2[0*512 + j], a0);
        a1 = fmaf(hv, w2[1*512 + j], a1);
        a2 = fmaf(hv, w2[2*512 + j], a2);
        a3 = fmaf(hv, w2[3*512 + j], a3);
    }
    #pragma unroll
    for (int off = 16; off; off >>= 1) {
        a0 += __shfl_xor_sync(0xffffffffu, a0, off);
        a1 += __shfl_xor_sync(0xffffffffu, a1, off);
        a2 += __shfl_xor_sync(0xffffffffu, a2, off);
        a3 += __shfl_xor_sync(0xffffffffu, a3, off);
    }
    __shared__ float red[4][4];
    if ((tid & 31) == 0) {
        int w = tid >> 5;
        red[w][0] = a0; red[w][1] = a1; red[w][2] = a2; red[w][3] = a3;
    }
    __syncthreads();
    if (tid < 4) {
        float acc = red[0][tid] + red[1][tid] + red[2][tid] + red[3][tid];
        g_bias16[m*4 + tid] = 16.f / (1.f + __expf(-acc));
    }
}

// ---------------------------------------------------------------------------
// 2) Expand (transposed): biasT[h][k][q] = bias16[rel_index[q*L+k]][h]
// ---------------------------------------------------------------------------
__global__ void k_expand(const int* __restrict__ rel_index)
{
    int i = blockIdx.x * blockDim.x + threadIdx.x;   // h<<16 | k<<8 | q
    if (i >= H*LQ*LQ) return;
    int h = i >> 16;
    int k = (i >> 8) & 255;
    int q = i & 255;
    g_biasT[i] = g_bias16[rel_index[q*LQ + k]*H + h];
}

// ---------------------------------------------------------------------------
// 3) Fused QKV GEMM + bias + cosine-normalize q,k.
//    192 threads; thread owns cols (c, c+192) x 32 rows.
// ---------------------------------------------------------------------------
__device__ __forceinline__ void qkv_epilogue(int c, const float* acc, int rowbase,
                                             const float* __restrict__ q_bias,
                                             const float* __restrict__ v_bias)
{
    if (c < 256) {
        const bool isq = (c < 128);
        const int cc = isq ? c : (c - 128);
        const int h = cc >> 5, d = cc & 31;
        const float bias = isq ? q_bias[c] : 0.f;
        float* dst = isq ? g_Q : g_K;
        #pragma unroll 4
        for (int r = 0; r < 32; r++) {
            float v = acc[r] + bias;
            float ss = v * v;
            #pragma unroll
            for (int off = 16; off; off >>= 1)
                ss += __shfl_xor_sync(0xffffffffu, ss, off);
            float inv = 1.f / fmaxf(sqrtf(ss), 1e-12f);
            int g = rowbase + r;
            int b = g >> 8, l = g & 255;
            dst[(((b*H + h)*LQ + l) << 5) + d] = v * inv;
        }
    } else {
        const int cc = c - 256;
        const int h = cc >> 5, d = cc & 31;
        const float bias = v_bias[cc];
        #pragma unroll 4
        for (int r = 0; r < 32; r++) {
            int g = rowbase + r;
            int b = g >> 8, l = g & 255;
            g_V[(((b*H + h)*LQ + l) << 5) + d] = acc[r] + bias;
        }
    }
}

__global__ void __launch_bounds__(192) k_qkv(const float* __restrict__ x,
                                             const float* __restrict__ qkv_w,
                                             const float* __restrict__ q_bias,
                                             const float* __restrict__ v_bias)
{
    __shared__ float xs[32][128];
    const int blk = blockIdx.x;           // 4096 blocks
    const long base = (long)blk * 32 * 128;
    const int tid = threadIdx.x;

    {
        const float4* src = (const float4*)(x + base);
        float4* dst4 = (float4*)xs;
        for (int i = tid; i < 1024; i += 192) dst4[i] = src[i];
    }
    __syncthreads();

    const int c0 = tid, c1 = tid + 192;
    const float4* wa4 = (const float4*)(qkv_w + c0 * 128);
    const float4* wb4 = (const float4*)(qkv_w + c1 * 128);
    float acc0[32], acc1[32];
    #pragma unroll
    for (int r = 0; r < 32; r++) { acc0[r] = 0.f; acc1[r] = 0.f; }

    for (int kk = 0; kk < 32; kk++) {
        float4 wa = wa4[kk];
        float4 wb = wb4[kk];
        #pragma unroll
        for (int r = 0; r < 32; r++) {
            float4 xv = ((const float4*)xs[r])[kk];
            acc0[r] = fmaf(xv.x, wa.x, fmaf(xv.y, wa.y, fmaf(xv.z, wa.z, fmaf(xv.w, wa.w, acc0[r]))));
            acc1[r] = fmaf(xv.x, wb.x, fmaf(xv.y, wb.y, fmaf(xv.z, wb.z, fmaf(xv.w, wb.w, acc1[r]))));
        }
    }

    const int rowbase = blk * 32;
    qkv_epilogue(c0, acc0, rowbase, q_bias, v_bias);
    qkv_epilogue(c1, acc1, rowbase, q_bias, v_bias);
}

// ---------------------------------------------------------------------------
// 4) Attention: block = (b,h); 128 threads, thread owns 2 query rows.
//    Broadcast K/V smem reads amortized over 2 queries.
//    Fixed-max softmax (provably safe: s<=scale+16, diag>=scale => lsum>=e^-16).
// ---------------------------------------------------------------------------
__global__ void __launch_bounds__(128) k_attn(const float* __restrict__ logit_scale)
{
    extern __shared__ float sm[];
    float* ksm = sm;            // 256*32
    float* vsm = sm + 8192;     // 256*32

    const int bh = blockIdx.x;            // b*H + h
    const int h = bh & 3;
    const long base = (long)bh * (LQ * HD);
    const int tid = threadIdx.x;

    {
        const float4* Ks = (const float4*)(g_K + base);
        const float4* Vs = (const float4*)(g_V + base);
        float4* k4 = (float4*)ksm;
        float4* v4 = (float4*)vsm;
        for (int i = tid; i < 2048; i += 128) { k4[i] = Ks[i]; v4[i] = Vs[i]; }
    }
    __syncthreads();

    const float scale = __expf(fminf(logit_scale[h], 4.6051702f)); // ln(100)
    const float fixmax = scale + 16.0f;

    float qv0[32], qv1[32];
    {
        const float4* q0p = (const float4*)(g_Q + base + (long)tid * HD);
        const float4* q1p = (const float4*)(g_Q + base + (long)(tid + 128) * HD);
        #pragma unroll
        for (int j = 0; j < 8; j++) {
            float4 a = q0p[j], b = q1p[j];
            qv0[4*j+0] = a.x; qv0[4*j+1] = a.y; qv0[4*j+2] = a.z; qv0[4*j+3] = a.w;
            qv1[4*j+0] = b.x; qv1[4*j+1] = b.y; qv1[4*j+2] = b.z; qv1[4*j+3] = b.w;
        }
    }

    const float* biasT = g_biasT + (h << 16) + tid;  // [h][k][q], q = tid / tid+128

    float lsum0 = 0.f, lsum1 = 0.f;
    float acc0[32], acc1[32];
    #pragma unroll
    for (int d = 0; d < 32; d++) { acc0[d] = 0.f; acc1[d] = 0.f; }

    for (int k = 0; k < LQ; k++) {
        const float4* kr = (const float4*)(ksm + k * HD);
        float s0 = 0.f, s1 = 0.f;
        #pragma unroll
        for (int j = 0; j < 8; j++) {
            float4 t = kr[j];
            s0 = fmaf(qv0[4*j+0], t.x, s0); s1 = fmaf(qv1[4*j+0], t.x, s1);
            s0 = fmaf(qv0[4*j+1], t.y, s0); s1 = fmaf(qv1[4*j+1], t.y, s1);
            s0 = fmaf(qv0[4*j+2], t.z, s0); s1 = fmaf(qv1[4*j+2], t.z, s1);
            s0 = fmaf(qv0[4*j+3], t.w, s0); s1 = fmaf(qv1[4*j+3], t.w, s1);
        }
        s0 = fmaf(s0, scale, biasT[k << 8]);
        s1 = fmaf(s1, scale, biasT[(k << 8) + 128]);

        float p0 = __expf(s0 - fixmax);
        float p1 = __expf(s1 - fixmax);
        lsum0 += p0; lsum1 += p1;
        const float4* vr = (const float4*)(vsm + k * HD);
        #pragma unroll
        for (int j = 0; j < 8; j++) {
            float4 t = vr[j];
            acc0[4*j+0] = fmaf(p0, t.x, acc0[4*j+0]); acc1[4*j+0] = fmaf(p1, t.x, acc1[4*j+0]);
            acc0[4*j+1] = fmaf(p0, t.y, acc0[4*j+1]); acc1[4*j+1] = fmaf(p1, t.y, acc1[4*j+1]);
            acc0[4*j+2] = fmaf(p0, t.z, acc0[4*j+2]); acc1[4*j+2] = fmaf(p1, t.z, acc1[4*j+2]);
            acc0[4*j+3] = fmaf(p0, t.w, acc0[4*j+3]); acc1[4*j+3] = fmaf(p1, t.w, acc1[4*j+3]);
        }
    }

    const float inv0 = 1.f / lsum0;
    const float inv1 = 1.f / lsum1;
    const int b = bh >> 2;
    float4* o0 = (float4*)(g_O + ((long)(b*LQ + tid) * C) + h * HD);
    float4* o1 = (float4*)(g_O + ((long)(b*LQ + tid + 128) * C) + h * HD);
    #pragma unroll
    for (int j = 0; j < 8; j++) {
        float4 t;
        t.x = acc0[4*j+0]*inv0; t.y = acc0[4*j+1]*inv0;
        t.z = acc0[4*j+2]*inv0; t.w = acc0[4*j+3]*inv0;
        o0[j] = t;
        t.x = acc1[4*j+0]*inv1; t.y = acc1[4*j+1]*inv1;
        t.z = acc1[4*j+2]*inv1; t.w = acc1[4*j+3]*inv1;
        o1[j] = t;
    }
}

// ---------------------------------------------------------------------------
// 5) Output projection: 64 threads; thread owns cols (c, c+64) x 32 rows.
// ---------------------------------------------------------------------------
__global__ void __launch_bounds__(64) k_proj(const float* __restrict__ proj_w,
                                             const float* __restrict__ proj_b,
                                             float* __restrict__ out)
{
    __shared__ float xs[32][128];
    const int blk = blockIdx.x;            // 4096 blocks of 32 rows
    const long base = (long)blk * 32 * 128;
    const int tid = threadIdx.x;

    {
        const float4* src = (const float4*)(g_O + base);
        float4* dst4 = (float4*)xs;
        for (int i = tid; i < 1024; i += 64) dst4[i] = src[i];
    }
    __syncthreads();

    const int c0 = tid, c1 = tid + 64;
    const float4* wa4 = (const float4*)(proj_w + c0 * 128);
    const float4* wb4 = (const float4*)(proj_w + c1 * 128);
    float acc0[32], acc1[32];
    #pragma unroll
    for (int r = 0; r < 32; r++) { acc0[r] = 0.f; acc1[r] = 0.f; }

    for (int kk = 0; kk < 32; kk++) {
        float4 wa = wa4[kk];
        float4 wb = wb4[kk];
        #pragma unroll
        for (int r = 0; r < 32; r++) {
            float4 xv = ((const float4*)xs[r])[kk];
            acc0[r] = fmaf(xv.x, wa.x, fmaf(xv.y, wa.y, fmaf(xv.z, wa.z, fmaf(xv.w, wa.w, acc0[r]))));
            acc1[r] = fmaf(xv.x, wb.x, fmaf(xv.y, wb.y, fmaf(xv.z, wb.z, fmaf(xv.w, wb.w, acc1[r]))));
        }
    }

    const float pb0 = proj_b[c0];
    const float pb1 = proj_b[c1];
    #pragma unroll 4
    for (int r = 0; r < 32; r++) {
        out[base + r * 128 + c0] = acc0[r] + pb0;
        out[base + r * 128 + c1] = acc1[r] + pb1;
    }
}

// ---------------------------------------------------------------------------
extern "C" void kernel_launch(void* const* d_in, const int* in_sizes, int n_in,
                              void* d_out, int out_size)
{
    const float* x           = (const float*)d_in[0];
    const float* qkv_w       = (const float*)d_in[1];
    const float* q_bias      = (const float*)d_in[2];
    const float* v_bias      = (const float*)d_in[3];
    const float* logit_scale = (const float*)d_in[4];
    const float* cpb_w1      = (const float*)d_in[5];
    const float* cpb_b1      = (const float*)d_in[6];
    const float* cpb_w2      = (const float*)d_in[7];
    const float* proj_w      = (const float*)d_in[8];
    const float* proj_b      = (const float*)d_in[9];
    const float* rel_table   = (const float*)d_in[10];
    const int*   rel_index   = (const int*)d_in[11];
    float* out = (float*)d_out;

    cudaFuncSetAttribute(k_attn, cudaFuncAttributeMaxDynamicSharedMemorySize, 64 * 1024);

    k_cpb<<<M_TAB, 128>>>(rel_table, cpb_w1, cpb_b1, cpb_w2);
    k_expand<<<(H*LQ*LQ) / 256, 256>>>(rel_index);
    k_qkv<<<ROWS_TOT / 32, 192>>>(x, qkv_w, q_bias, v_bias);
    k_attn<<<BW * H, 128, 64 * 1024>>>(logit_scale);
    k_proj<<<ROWS_TOT / 32, 64>>>(proj_w, proj_b, out);
}

// round 15
// speedup vs baseline: 1.7350x; 1.4417x over previous
#include <cuda_runtime.h>
#include <cuda_fp16.h>
#include <math.h>

// Problem constants
#define BW    512
#define LQ    256
#define C     128
#define H     4
#define HD    32
#define M_TAB 1575
#define ROWS_TOT (BW*LQ)   // 131072

// Device-global scratch
__device__ float g_Q[BW*H*LQ*HD];
__device__ float g_K[BW*H*LQ*HD];
__device__ float g_V[BW*H*LQ*HD];
__device__ float g_O[BW*LQ*C];
__device__ float g_bias16[M_TAB*H];
__device__ float g_biasF[H*LQ*LQ];   // [h][q][k]

// ---------------------------------------------------------------------------
// helpers
// ---------------------------------------------------------------------------
__device__ __forceinline__ float tf32r(float f) {
    unsigned u;
    asm("cvt.rna.tf32.f32 %0, %1;" : "=r"(u) : "f"(f));
    return __uint_as_float(u);
}
__device__ __forceinline__ unsigned tf32u(float f) {
    unsigned u;
    asm("cvt.rna.tf32.f32 %0, %1;" : "=r"(u) : "f"(f));
    return u;
}
__device__ __forceinline__ unsigned packh2(float lo, float hi) {
    unsigned r;
    asm("cvt.rn.f16x2.f32 %0, %1, %2;" : "=r"(r) : "f"(hi), "f"(lo));
    return r;
}
__device__ __forceinline__ void mma_tf32(float* c, const unsigned* a, unsigned b0, unsigned b1) {
    asm volatile("mma.sync.aligned.m16n8k8.row.col.f32.tf32.tf32.f32 "
                 "{%0,%1,%2,%3},{%4,%5,%6,%7},{%8,%9},{%0,%1,%2,%3};"
                 : "+f"(c[0]), "+f"(c[1]), "+f"(c[2]), "+f"(c[3])
                 : "r"(a[0]), "r"(a[1]), "r"(a[2]), "r"(a[3]), "r"(b0), "r"(b1));
}
__device__ __forceinline__ void mma_f16(float* c, unsigned a0, unsigned a1, unsigned a2, unsigned a3,
                                        unsigned b0, unsigned b1) {
    asm volatile("mma.sync.aligned.m16n8k16.row.col.f32.f16.f16.f32 "
                 "{%0,%1,%2,%3},{%4,%5,%6,%7},{%8,%9},{%0,%1,%2,%3};"
                 : "+f"(c[0]), "+f"(c[1]), "+f"(c[2]), "+f"(c[3])
                 : "r"(a0), "r"(a1), "r"(a2), "r"(a3), "r"(b0), "r"(b1));
}
// split f into tf32 hi + tf32 lo (3xtf32 trick)
__device__ __forceinline__ void tf32split(float f, unsigned& hi, unsigned& lo) {
    hi = tf32u(f);
    lo = tf32u(f - __uint_as_float(hi));
}

// ---------------------------------------------------------------------------
// 1) CPB MLP, block per m
// ---------------------------------------------------------------------------
__global__ void __launch_bounds__(128) k_cpb(const float* __restrict__ rel_table,
                                             const float* __restrict__ w1,
                                             const float* __restrict__ b1,
                                             const float* __restrict__ w2)
{
    const int m = blockIdx.x;
    const int tid = threadIdx.x;
    const float t0 = rel_table[m*3+0], t1 = rel_table[m*3+1], t2 = rel_table[m*3+2];

    float a0 = 0.f, a1 = 0.f, a2 = 0.f, a3 = 0.f;
    for (int j = tid; j < 512; j += 128) {
        float hv = fmaf(t0, w1[j*3+0], fmaf(t1, w1[j*3+1], fmaf(t2, w1[j*3+2], b1[j])));
        hv = fmaxf(hv, 0.f);
        a0 = fmaf(hv, w2[0*512 + j], a0);
        a1 = fmaf(hv, w2[1*512 + j], a1);
        a2 = fmaf(hv, w2[2*512 + j], a2);
        a3 = fmaf(hv, w2[3*512 + j], a3);
    }
    #pragma unroll
    for (int off = 16; off; off >>= 1) {
        a0 += __shfl_xor_sync(0xffffffffu, a0, off);
        a1 += __shfl_xor_sync(0xffffffffu, a1, off);
        a2 += __shfl_xor_sync(0xffffffffu, a2, off);
        a3 += __shfl_xor_sync(0xffffffffu, a3, off);
    }
    __shared__ float red[4][4];
    if ((tid & 31) == 0) {
        int w = tid >> 5;
        red[w][0] = a0; red[w][1] = a1; red[w][2] = a2; red[w][3] = a3;
    }
    __syncthreads();
    if (tid < 4) {
        float acc = red[0][tid] + red[1][tid] + red[2][tid] + red[3][tid];
        g_bias16[m*4 + tid] = 16.f / (1.f + __expf(-acc));
    }
}

// ---------------------------------------------------------------------------
// 2) Expand: biasF[h][q][k] = bias16[rel_index[q*L+k]][h]
// ---------------------------------------------------------------------------
__global__ void k_expand(const int* __restrict__ rel_index)
{
    int i = blockIdx.x * blockDim.x + threadIdx.x;   // h<<16 | q<<8 | k
    if (i >= H*LQ*LQ) return;
    int h = i >> 16;
    int qk = i & 0xFFFF;
    g_biasF[i] = g_bias16[rel_index[qk]*H + h];
}

// ---------------------------------------------------------------------------
// 3) QKV GEMM (3xtf32 mma) + bias + cosine normalize.
//    Block tile 64(M) x 64(N), 4 warps (2x2), warp tile 32x32.
//    smem holds RAW fp32; hi/lo split at frag prep.
// ---------------------------------------------------------------------------
#define GEMM_SMEM (2 * 64 * 132 * 4)

__global__ void __launch_bounds__(128) k_qkv(const float* __restrict__ x,
                                             const float* __restrict__ qkv_w,
                                             const float* __restrict__ q_bias,
                                             const float* __restrict__ v_bias)
{
    extern __shared__ char smraw[];
    float* Xs = (float*)smraw;                 // [64][132]
    float* Ws = (float*)(smraw + 64*132*4);    // [64][132]

    const int tid = threadIdx.x;
    const int lane = tid & 31;
    const int warp = tid >> 5;
    const int wm = (warp & 1) * 32;
    const int wn = (warp >> 1) * 32;
    const int mbase = blockIdx.x * 64;
    const int nbase = blockIdx.y * 64;

    // load tiles (raw fp32)
    {
        const float4* src = (const float4*)(x + (long)mbase * 128);
        for (int i = tid; i < 2048; i += 128)
            *(float4*)(Xs + (i >> 5) * 132 + ((i & 31) << 2)) = src[i];
        const float4* wsrc = (const float4*)(qkv_w + (long)nbase * 128);
        for (int i = tid; i < 2048; i += 128)
            *(float4*)(Ws + (i >> 5) * 132 + ((i & 31) << 2)) = wsrc[i];
    }
    __syncthreads();

    float acc[2][4][4];
    #pragma unroll
    for (int i = 0; i < 2; i++)
        #pragma unroll
        for (int j = 0; j < 4; j++)
            #pragma unroll
            for (int r = 0; r < 4; r++) acc[i][j][r] = 0.f;

    #pragma unroll 2
    for (int ks = 0; ks < 16; ks++) {
        unsigned ah[2][4], al[2][4];
        #pragma unroll
        for (int mf = 0; mf < 2; mf++) {
            int r = wm + mf*16 + (lane >> 2);
            int cc = ks*8 + (lane & 3);
            tf32split(Xs[r*132 + cc],        ah[mf][0], al[mf][0]);
            tf32split(Xs[(r+8)*132 + cc],    ah[mf][1], al[mf][1]);
            tf32split(Xs[r*132 + cc + 4],    ah[mf][2], al[mf][2]);
            tf32split(Xs[(r+8)*132 + cc + 4],ah[mf][3], al[mf][3]);
        }
        #pragma unroll
        for (int nf = 0; nf < 4; nf++) {
            int n = wn + nf*8 + (lane >> 2);
            int cc = ks*8 + (lane & 3);
            unsigned bh0, bl0, bh1, bl1;
            tf32split(Ws[n*132 + cc],     bh0, bl0);
            tf32split(Ws[n*132 + cc + 4], bh1, bl1);
            mma_tf32(acc[0][nf], ah[0], bh0, bh1);
            mma_tf32(acc[0][nf], ah[0], bl0, bl1);
            mma_tf32(acc[0][nf], al[0], bh0, bh1);
            mma_tf32(acc[1][nf], ah[1], bh0, bh1);
            mma_tf32(acc[1][nf], ah[1], bl0, bl1);
            mma_tf32(acc[1][nf], al[1], bh0, bh1);
        }
    }

    // epilogue
    const int colg0 = nbase + wn;          // multiple of 32
    const int sect = colg0 >> 7;           // 0=q, 1=k, 2=v
    const int cs = colg0 & 127;
    const int hh = cs >> 5;

    float bias2[4][2];
    #pragma unroll
    for (int nf = 0; nf < 4; nf++) {
        int cg = cs + nf*8 + 2*(lane & 3);
        if (sect == 0)      { bias2[nf][0] = q_bias[cg]; bias2[nf][1] = q_bias[cg+1]; }
        else if (sect == 2) { bias2[nf][0] = v_bias[cg]; bias2[nf][1] = v_bias[cg+1]; }
        else                { bias2[nf][0] = 0.f; bias2[nf][1] = 0.f; }
    }

    #pragma unroll
    for (int mf = 0; mf < 2; mf++) {
        #pragma unroll
        for (int sub = 0; sub < 2; sub++) {
            int m = mbase + wm + mf*16 + sub*8 + (lane >> 2);
            int b = m >> 8, ltok = m & 255;
            float v8[8];
            float ss = 0.f;
            #pragma unroll
            for (int nf = 0; nf < 4; nf++) {
                float v0 = acc[mf][nf][2*sub]   + bias2[nf][0];
                float v1 = acc[mf][nf][2*sub+1] + bias2[nf][1];
                v8[2*nf] = v0; v8[2*nf+1] = v1;
                ss = fmaf(v0, v0, fmaf(v1, v1, ss));
            }
            if (sect < 2) {
                ss += __shfl_xor_sync(0xffffffffu, ss, 1);
                ss += __shfl_xor_sync(0xffffffffu, ss, 2);
                float inv = 1.f / fmaxf(sqrtf(ss), 1e-12f);
                float* dst = (sect == 0 ? g_Q : g_K) + (((long)(b*H + hh) * LQ + ltok) << 5);
                #pragma unroll
                for (int nf = 0; nf < 4; nf++) {
                    int d = nf*8 + 2*(lane & 3);
                    float2 t = make_float2(v8[2*nf]*inv, v8[2*nf+1]*inv);
                    *(float2*)(dst + d) = t;
                }
            } else {
                float* dst = g_V + (((long)(b*H + hh) * LQ + ltok) << 5);
                #pragma unroll
                for (int nf = 0; nf < 4; nf++) {
                    int d = nf*8 + 2*(lane & 3);
                    float2 t = make_float2(v8[2*nf], v8[2*nf+1]);
                    *(float2*)(dst + d) = t;
                }
            }
        }
    }
}

// ---------------------------------------------------------------------------
// 4) Attention (tensor cores).
//    Block = half a (b,h): 128 q-rows, 4 warps x 32 rows. grid = 2048*2.
//    K raw fp32 in smem [key][36-pad]; V^T fp16 [d][264-pad].
//    S = Qn Kn^T via 3xtf32 mma; ONLINE-MAX softmax (p in (0,1] -> fp16 safe);
//    P fp16 (C->A frag identity) @ V via f16 mma, f32 accum.
// ---------------------------------------------------------------------------
#define ATTN_KSM_BYTES (256*36*4)             // 36864
#define ATTN_SMEM (ATTN_KSM_BYTES + 32*264*2) // 53760

__global__ void __launch_bounds__(128) k_attn(const float* __restrict__ logit_scale)
{
    extern __shared__ char smraw[];
    float* Ksm = (float*)smraw;                         // [256][36] raw fp32
    __half* Vt = (__half*)(smraw + ATTN_KSM_BYTES);     // [32][264]

    const int bx = blockIdx.x;
    const int bh = bx >> 1;
    const int halfid = bx & 1;
    const int h = bh & 3;
    const long base = (long)bh * (LQ * HD);
    const int tid = threadIdx.x;
    const int lane = tid & 31;
    const int warp = tid >> 5;

    {
        const float4* Ks4 = (const float4*)(g_K + base);
        for (int i = tid; i < 2048; i += 128)
            *(float4*)(Ksm + (i >> 3) * 36 + ((i & 7) << 2)) = Ks4[i];
        const float* Vp = g_V + base;
        for (int i = tid; i < 8192; i += 128) {
            int key = i >> 5, d = i & 31;
            Vt[d*264 + key] = __float2half(Vp[i]);
        }
    }
    __syncthreads();

    const float scale = __expf(fminf(logit_scale[h], 4.6051702f));
    const int qrow0 = halfid * 128 + warp * 32;

    // Q frags: 3xtf32 hi/lo
    unsigned qh[2][4][4], ql[2][4][4];
    {
        const float* Qp = g_Q + base;
        #pragma unroll
        for (int mf = 0; mf < 2; mf++) {
            int r = qrow0 + mf*16 + (lane >> 2);
            #pragma unroll
            for (int ks = 0; ks < 4; ks++) {
                int cc = ks*8 + (lane & 3);
                tf32split(Qp[r*32 + cc],        qh[mf][ks][0], ql[mf][ks][0]);
                tf32split(Qp[(r+8)*32 + cc],    qh[mf][ks][1], ql[mf][ks][1]);
                tf32split(Qp[r*32 + cc + 4],    qh[mf][ks][2], ql[mf][ks][2]);
                tf32split(Qp[(r+8)*32 + cc + 4],qh[mf][ks][3], ql[mf][ks][3]);
            }
        }
    }

    float o[2][4][4];
    #pragma unroll
    for (int i = 0; i < 2; i++)
        #pragma unroll
        for (int j = 0; j < 4; j++)
            #pragma unroll
            for (int r = 0; r < 4; r++) o[i][j][r] = 0.f;
    float rsum[4] = {0.f, 0.f, 0.f, 0.f};
    float M[4] = {-1e30f, -1e30f, -1e30f, -1e30f};   // running row max per (mf,sub)

    const float* biasH = g_biasF + (h << 16);

    for (int tile = 0; tile < 4; tile++) {
        const int kt = tile * 64;
        float s[2][8][4];
        #pragma unroll
        for (int i = 0; i < 2; i++)
            #pragma unroll
            for (int j = 0; j < 8; j++)
                #pragma unroll
                for (int r = 0; r < 4; r++) s[i][j][r] = 0.f;

        // S = Q K^T, 3xtf32
        #pragma unroll
        for (int ks = 0; ks < 4; ks++) {
            #pragma unroll
            for (int nf = 0; nf < 8; nf++) {
                int key = kt + nf*8 + (lane >> 2);
                int dd = ks*8 + (lane & 3);
                unsigned bh0, bl0, bh1, bl1;
                tf32split(Ksm[key*36 + dd],     bh0, bl0);
                tf32split(Ksm[key*36 + dd + 4], bh1, bl1);
                mma_tf32(s[0][nf], qh[0][ks], bh0, bh1);
                mma_tf32(s[0][nf], qh[0][ks], bl0, bl1);
                mma_tf32(s[0][nf], ql[0][ks], bh0, bh1);
                mma_tf32(s[1][nf], qh[1][ks], bh0, bh1);
                mma_tf32(s[1][nf], qh[1][ks], bl0, bl1);
                mma_tf32(s[1][nf], ql[1][ks], bh0, bh1);
            }
        }

        // logits = s*scale + bias; per-row tile max
        float tmax[4] = {-1e30f, -1e30f, -1e30f, -1e30f};
        #pragma unroll
        for (int mf = 0; mf < 2; mf++) {
            int r0 = qrow0 + mf*16 + (lane >> 2);
            #pragma unroll
            for (int nf = 0; nf < 8; nf++) {
                int k0 = kt + nf*8 + 2*(lane & 3);
                float2 bA = *(const float2*)(biasH + r0*256 + k0);
                float2 bB = *(const float2*)(biasH + (r0+8)*256 + k0);
                s[mf][nf][0] = fmaf(s[mf][nf][0], scale, bA.x);
                s[mf][nf][1] = fmaf(s[mf][nf][1], scale, bA.y);
                s[mf][nf][2] = fmaf(s[mf][nf][2], scale, bB.x);
                s[mf][nf][3] = fmaf(s[mf][nf][3], scale, bB.y);
                tmax[mf*2+0] = fmaxf(tmax[mf*2+0], fmaxf(s[mf][nf][0], s[mf][nf][1]));
                tmax[mf*2+1] = fmaxf(tmax[mf*2+1], fmaxf(s[mf][nf][2], s[mf][nf][3]));
            }
        }
        #pragma unroll
        for (int g = 0; g < 4; g++) {
            tmax[g] = fmaxf(tmax[g], __shfl_xor_sync(0xffffffffu, tmax[g], 1));
            tmax[g] = fmaxf(tmax[g], __shfl_xor_sync(0xffffffffu, tmax[g], 2));
        }
        // rescale running state
        float corr[4];
        #pragma unroll
        for (int g = 0; g < 4; g++) {
            float Mn = fmaxf(M[g], tmax[g]);
            corr[g] = __expf(M[g] - Mn);
            M[g] = Mn;
            rsum[g] *= corr[g];
        }
        #pragma unroll
        for (int mf = 0; mf < 2; mf++)
            #pragma unroll
            for (int nf2 = 0; nf2 < 4; nf2++) {
                o[mf][nf2][0] *= corr[mf*2+0];
                o[mf][nf2][1] *= corr[mf*2+0];
                o[mf][nf2][2] *= corr[mf*2+1];
                o[mf][nf2][3] *= corr[mf*2+1];
            }

        // p = exp(logit - M), pack fp16, accumulate rsum
        unsigned ph[2][8][2];
        #pragma unroll
        for (int mf = 0; mf < 2; mf++) {
            #pragma unroll
            for (int nf = 0; nf < 8; nf++) {
                float p0 = __expf(s[mf][nf][0] - M[mf*2+0]);
                float p1 = __expf(s[mf][nf][1] - M[mf*2+0]);
                float p2 = __expf(s[mf][nf][2] - M[mf*2+1]);
                float p3 = __expf(s[mf][nf][3] - M[mf*2+1]);
                rsum[mf*2+0] += p0 + p1;
                rsum[mf*2+1] += p2 + p3;
                ph[mf][nf][0] = packh2(p0, p1);
                ph[mf][nf][1] = packh2(p2, p3);
            }
        }

        // O += P V
        #pragma unroll
        for (int kk = 0; kk < 4; kk++) {
            int key0 = kt + kk*16 + 2*(lane & 3);
            #pragma unroll
            for (int nf2 = 0; nf2 < 4; nf2++) {
                int n = nf2*8 + (lane >> 2);
                unsigned vb0 = *(const unsigned*)(Vt + n*264 + key0);
                unsigned vb1 = *(const unsigned*)(Vt + n*264 + key0 + 8);
                mma_f16(o[0][nf2], ph[0][2*kk][0], ph[0][2*kk][1],
                        ph[0][2*kk+1][0], ph[0][2*kk+1][1], vb0, vb1);
                mma_f16(o[1][nf2], ph[1][2*kk][0], ph[1][2*kk][1],
                        ph[1][2*kk+1][0], ph[1][2*kk+1][1], vb0, vb1);
            }
        }
    }

    // reduce row sums over quad lanes
    #pragma unroll
    for (int i = 0; i < 4; i++) {
        rsum[i] += __shfl_xor_sync(0xffffffffu, rsum[i], 1);
        rsum[i] += __shfl_xor_sync(0xffffffffu, rsum[i], 2);
        rsum[i] = 1.f / rsum[i];
    }

    const int b = bh >> 2;
    #pragma unroll
    for (int mf = 0; mf < 2; mf++) {
        #pragma unroll
        for (int sub = 0; sub < 2; sub++) {
            int row = qrow0 + mf*16 + sub*8 + (lane >> 2);
            float inv = rsum[mf*2 + sub];
            float* dst = g_O + ((long)(b*LQ + row) * C) + h * HD;
            #pragma unroll
            for (int nf2 = 0; nf2 < 4; nf2++) {
                int d = nf2*8 + 2*(lane & 3);
                float2 t = make_float2(o[mf][nf2][2*sub] * inv,
                                       o[mf][nf2][2*sub+1] * inv);
                *(float2*)(dst + d) = t;
            }
        }
    }
}

// ---------------------------------------------------------------------------
// 5) Output projection (single tf32 mma): out = O @ proj_w^T + proj_b
// ---------------------------------------------------------------------------
__global__ void __launch_bounds__(128) k_proj(const float* __restrict__ proj_w,
                                              const float* __restrict__ proj_b,
                                              float* __restrict__ out)
{
    extern __shared__ char smraw[];
    float* Xs = (float*)smraw;
    float* Ws = (float*)(smraw + 64*132*4);

    const int tid = threadIdx.x;
    const int lane = tid & 31;
    const int warp = tid >> 5;
    const int wm = (warp & 1) * 32;
    const int wn = (warp >> 1) * 32;
    const int mbase = blockIdx.x * 64;
    const int nbase = blockIdx.y * 64;

    {
        const float4* src = (const float4*)(g_O + (long)mbase * 128);
        for (int i = tid; i < 2048; i += 128) {
            float4 v = src[i];
            v.x = tf32r(v.x); v.y = tf32r(v.y); v.z = tf32r(v.z); v.w = tf32r(v.w);
            *(float4*)(Xs + (i >> 5) * 132 + ((i & 31) << 2)) = v;
        }
        const float4* wsrc = (const float4*)(proj_w + (long)nbase * 128);
        for (int i = tid; i < 2048; i += 128) {
            float4 v = wsrc[i];
            v.x = tf32r(v.x); v.y = tf32r(v.y); v.z = tf32r(v.z); v.w = tf32r(v.w);
            *(float4*)(Ws + (i >> 5) * 132 + ((i & 31) << 2)) = v;
        }
    }
    __syncthreads();

    float acc[2][4][4];
    #pragma unroll
    for (int i = 0; i < 2; i++)
        #pragma unroll
        for (int j = 0; j < 4; j++)
            #pragma unroll
            for (int r = 0; r < 4; r++) acc[i][j][r] = 0.f;

    #pragma unroll 4
    for (int ks = 0; ks < 16; ks++) {
        unsigned a[2][4];
        #pragma unroll
        for (int mf = 0; mf < 2; mf++) {
            int r = wm + mf*16 + (lane >> 2);
            int cc = ks*8 + (lane & 3);
            a[mf][0] = __float_as_uint(Xs[r*132 + cc]);
            a[mf][1] = __float_as_uint(Xs[(r+8)*132 + cc]);
            a[mf][2] = __float_as_uint(Xs[r*132 + cc + 4]);
            a[mf][3] = __float_as_uint(Xs[(r+8)*132 + cc + 4]);
        }
        #pragma unroll
        for (int nf = 0; nf < 4; nf++) {
            int n = wn + nf*8 + (lane >> 2);
            int cc = ks*8 + (lane & 3);
            unsigned b0 = __float_as_uint(Ws[n*132 + cc]);
            unsigned b1 = __float_as_uint(Ws[n*132 + cc + 4]);
            mma_tf32(acc[0][nf], a[0], b0, b1);
            mma_tf32(acc[1][nf], a[1], b0, b1);
        }
    }

    const int colg0 = nbase + wn;
    float pb[4][2];
    #pragma unroll
    for (int nf = 0; nf < 4; nf++) {
        int cg = colg0 + nf*8 + 2*(lane & 3);
        pb[nf][0] = proj_b[cg];
        pb[nf][1] = proj_b[cg+1];
    }

    #pragma unroll
    for (int mf = 0; mf < 2; mf++) {
        #pragma unroll
        for (int sub = 0; sub < 2; sub++) {
            int m = mbase + wm + mf*16 + sub*8 + (lane >> 2);
            #pragma unroll
            for (int nf = 0; nf < 4; nf++) {
                int cg = colg0 + nf*8 + 2*(lane & 3);
                float2 t = make_float2(acc[mf][nf][2*sub]   + pb[nf][0],
                                       acc[mf][nf][2*sub+1] + pb[nf][1]);
                *(float2*)(out + (long)m * 128 + cg) = t;
            }
        }
    }
}

// ---------------------------------------------------------------------------
extern "C" void kernel_launch(void* const* d_in, const int* in_sizes, int n_in,
                              void* d_out, int out_size)
{
    const float* x           = (const float*)d_in[0];
    const float* qkv_w       = (const float*)d_in[1];
    const float* q_bias      = (const float*)d_in[2];
    const float* v_bias      = (const float*)d_in[3];
    const float* logit_scale = (const float*)d_in[4];
    const float* cpb_w1      = (const float*)d_in[5];
    const float* cpb_b1      = (const float*)d_in[6];
    const float* cpb_w2      = (const float*)d_in[7];
    const float* proj_w      = (const float*)d_in[8];
    const float* proj_b      = (const float*)d_in[9];
    const float* rel_table   = (const float*)d_in[10];
    const int*   rel_index   = (const int*)d_in[11];
    float* out = (float*)d_out;

    cudaFuncSetAttribute(k_qkv,  cudaFuncAttributeMaxDynamicSharedMemorySize, GEMM_SMEM);
    cudaFuncSetAttribute(k_proj, cudaFuncAttributeMaxDynamicSharedMemorySize, GEMM_SMEM);
    cudaFuncSetAttribute(k_attn, cudaFuncAttributeMaxDynamicSharedMemorySize, ATTN_SMEM);

    k_cpb<<<M_TAB, 128>>>(rel_table, cpb_w1, cpb_b1, cpb_w2);
    k_expand<<<(H*LQ*LQ) / 256, 256>>>(rel_index);
    k_qkv<<<dim3(ROWS_TOT/64, 6), 128, GEMM_SMEM>>>(x, qkv_w, q_bias, v_bias);
    k_attn<<<BW * H * 2, 128, ATTN_SMEM>>>(logit_scale);
    k_proj<<<dim3(ROWS_TOT/64, 2), 128, GEMM_SMEM>>>(proj_w, proj_b, out);
}

// round 16
// speedup vs baseline: 1.7704x; 1.0204x over previous
#include <cuda_runtime.h>
#include <cuda_fp16.h>
#include <math.h>

// Problem constants
#define BW    512
#define LQ    256
#define C     128
#define H     4
#define HD    32
#define M_TAB 1575
#define ROWS_TOT (BW*LQ)   // 131072

// Device-global scratch
__device__ float g_Q[BW*H*LQ*HD];
__device__ float g_K[BW*H*LQ*HD];
__device__ float g_V[BW*H*LQ*HD];
__device__ float g_O[BW*LQ*C];
__device__ float g_bias16[M_TAB*H];
__device__ float g_biasF[H*LQ*LQ];   // [h][q][k]

// ---------------------------------------------------------------------------
// helpers
// ---------------------------------------------------------------------------
__device__ __forceinline__ float tf32r(float f) {
    unsigned u;
    asm("cvt.rna.tf32.f32 %0, %1;" : "=r"(u) : "f"(f));
    return __uint_as_float(u);
}
__device__ __forceinline__ unsigned tf32u(float f) {
    unsigned u;
    asm("cvt.rna.tf32.f32 %0, %1;" : "=r"(u) : "f"(f));
    return u;
}
__device__ __forceinline__ unsigned packh2(float lo, float hi) {
    unsigned r;
    asm("cvt.rn.f16x2.f32 %0, %1, %2;" : "=r"(r) : "f"(hi), "f"(lo));
    return r;
}
__device__ __forceinline__ void mma_tf32(float* c, const unsigned* a, unsigned b0, unsigned b1) {
    asm volatile("mma.sync.aligned.m16n8k8.row.col.f32.tf32.tf32.f32 "
                 "{%0,%1,%2,%3},{%4,%5,%6,%7},{%8,%9},{%0,%1,%2,%3};"
                 : "+f"(c[0]), "+f"(c[1]), "+f"(c[2]), "+f"(c[3])
                 : "r"(a[0]), "r"(a[1]), "r"(a[2]), "r"(a[3]), "r"(b0), "r"(b1));
}
__device__ __forceinline__ void mma_f16(float* c, unsigned a0, unsigned a1, unsigned a2, unsigned a3,
                                        unsigned b0, unsigned b1) {
    asm volatile("mma.sync.aligned.m16n8k16.row.col.f32.f16.f16.f32 "
                 "{%0,%1,%2,%3},{%4,%5,%6,%7},{%8,%9},{%0,%1,%2,%3};"
                 : "+f"(c[0]), "+f"(c[1]), "+f"(c[2]), "+f"(c[3])
                 : "r"(a0), "r"(a1), "r"(a2), "r"(a3), "r"(b0), "r"(b1));
}
// split f into tf32 hi + tf32 lo (3xtf32 trick)
__device__ __forceinline__ void tf32split(float f, unsigned& hi, unsigned& lo) {
    hi = tf32u(f);
    lo = tf32u(f - __uint_as_float(hi));
}

// ---------------------------------------------------------------------------
// 1) CPB MLP, block per m
// ---------------------------------------------------------------------------
__global__ void __launch_bounds__(128) k_cpb(const float* __restrict__ rel_table,
                                             const float* __restrict__ w1,
                                             const float* __restrict__ b1,
                                             const float* __restrict__ w2)
{
    const int m = blockIdx.x;
    const int tid = threadIdx.x;
    const float t0 = rel_table[m*3+0], t1 = rel_table[m*3+1], t2 = rel_table[m*3+2];

    float a0 = 0.f, a1 = 0.f, a2 = 0.f, a3 = 0.f;
    for (int j = tid; j < 512; j += 128) {
        float hv = fmaf(t0, w1[j*3+0], fmaf(t1, w1[j*3+1], fmaf(t2, w1[j*3+2], b1[j])));
        hv = fmaxf(hv, 0.f);
        a0 = fmaf(hv, w2[0*512 + j], a0);
        a1 = fmaf(hv, w2[1*512 + j], a1);
        a2 = fmaf(hv, w2[2*512 + j], a2);
        a3 = fmaf(hv, w2[3*512 + j], a3);
    }
    #pragma unroll
    for (int off = 16; off; off >>= 1) {
        a0 += __shfl_xor_sync(0xffffffffu, a0, off);
        a1 += __shfl_xor_sync(0xffffffffu, a1, off);
        a2 += __shfl_xor_sync(0xffffffffu, a2, off);
        a3 += __shfl_xor_sync(0xffffffffu, a3, off);
    }
    __shared__ float red[4][4];
    if ((tid & 31) == 0) {
        int w = tid >> 5;
        red[w][0] = a0; red[w][1] = a1; red[w][2] = a2; red[w][3] = a3;
    }
    __syncthreads();
    if (tid < 4) {
        float acc = red[0][tid] + red[1][tid] + red[2][tid] + red[3][tid];
        g_bias16[m*4 + tid] = 16.f / (1.f + __expf(-acc));
    }
}

// ---------------------------------------------------------------------------
// 2) Expand: biasF[h][q][k] = bias16[rel_index[q*L+k]][h]
// ---------------------------------------------------------------------------
__global__ void k_expand(const int* __restrict__ rel_index)
{
    int i = blockIdx.x * blockDim.x + threadIdx.x;   // h<<16 | q<<8 | k
    if (i >= H*LQ*LQ) return;
    int h = i >> 16;
    int qk = i & 0xFFFF;
    g_biasF[i] = g_bias16[rel_index[qk]*H + h];
}

// ---------------------------------------------------------------------------
// 3) QKV GEMM (3xtf32 mma) + bias + cosine normalize.  (unchanged from R15)
// ---------------------------------------------------------------------------
#define GEMM_SMEM (2 * 64 * 132 * 4)

__global__ void __launch_bounds__(128) k_qkv(const float* __restrict__ x,
                                             const float* __restrict__ qkv_w,
                                             const float* __restrict__ q_bias,
                                             const float* __restrict__ v_bias)
{
    extern __shared__ char smraw[];
    float* Xs = (float*)smraw;                 // [64][132]
    float* Ws = (float*)(smraw + 64*132*4);    // [64][132]

    const int tid = threadIdx.x;
    const int lane = tid & 31;
    const int warp = tid >> 5;
    const int wm = (warp & 1) * 32;
    const int wn = (warp >> 1) * 32;
    const int mbase = blockIdx.x * 64;
    const int nbase = blockIdx.y * 64;

    {
        const float4* src = (const float4*)(x + (long)mbase * 128);
        for (int i = tid; i < 2048; i += 128)
            *(float4*)(Xs + (i >> 5) * 132 + ((i & 31) << 2)) = src[i];
        const float4* wsrc = (const float4*)(qkv_w + (long)nbase * 128);
        for (int i = tid; i < 2048; i += 128)
            *(float4*)(Ws + (i >> 5) * 132 + ((i & 31) << 2)) = wsrc[i];
    }
    __syncthreads();

    float acc[2][4][4];
    #pragma unroll
    for (int i = 0; i < 2; i++)
        #pragma unroll
        for (int j = 0; j < 4; j++)
            #pragma unroll
            for (int r = 0; r < 4; r++) acc[i][j][r] = 0.f;

    #pragma unroll 2
    for (int ks = 0; ks < 16; ks++) {
        unsigned ah[2][4], al[2][4];
        #pragma unroll
        for (int mf = 0; mf < 2; mf++) {
            int r = wm + mf*16 + (lane >> 2);
            int cc = ks*8 + (lane & 3);
            tf32split(Xs[r*132 + cc],        ah[mf][0], al[mf][0]);
            tf32split(Xs[(r+8)*132 + cc],    ah[mf][1], al[mf][1]);
            tf32split(Xs[r*132 + cc + 4],    ah[mf][2], al[mf][2]);
            tf32split(Xs[(r+8)*132 + cc + 4],ah[mf][3], al[mf][3]);
        }
        #pragma unroll
        for (int nf = 0; nf < 4; nf++) {
            int n = wn + nf*8 + (lane >> 2);
            int cc = ks*8 + (lane & 3);
            unsigned bh0, bl0, bh1, bl1;
            tf32split(Ws[n*132 + cc],     bh0, bl0);
            tf32split(Ws[n*132 + cc + 4], bh1, bl1);
            mma_tf32(acc[0][nf], ah[0], bh0, bh1);
            mma_tf32(acc[0][nf], ah[0], bl0, bl1);
            mma_tf32(acc[0][nf], al[0], bh0, bh1);
            mma_tf32(acc[1][nf], ah[1], bh0, bh1);
            mma_tf32(acc[1][nf], ah[1], bl0, bl1);
            mma_tf32(acc[1][nf], al[1], bh0, bh1);
        }
    }

    const int colg0 = nbase + wn;          // multiple of 32
    const int sect = colg0 >> 7;           // 0=q, 1=k, 2=v
    const int cs = colg0 & 127;
    const int hh = cs >> 5;

    float bias2[4][2];
    #pragma unroll
    for (int nf = 0; nf < 4; nf++) {
        int cg = cs + nf*8 + 2*(lane & 3);
        if (sect == 0)      { bias2[nf][0] = q_bias[cg]; bias2[nf][1] = q_bias[cg+1]; }
        else if (sect == 2) { bias2[nf][0] = v_bias[cg]; bias2[nf][1] = v_bias[cg+1]; }
        else                { bias2[nf][0] = 0.f; bias2[nf][1] = 0.f; }
    }

    #pragma unroll
    for (int mf = 0; mf < 2; mf++) {
        #pragma unroll
        for (int sub = 0; sub < 2; sub++) {
            int m = mbase + wm + mf*16 + sub*8 + (lane >> 2);
            int b = m >> 8, ltok = m & 255;
            float v8[8];
            float ss = 0.f;
            #pragma unroll
            for (int nf = 0; nf < 4; nf++) {
                float v0 = acc[mf][nf][2*sub]   + bias2[nf][0];
                float v1 = acc[mf][nf][2*sub+1] + bias2[nf][1];
                v8[2*nf] = v0; v8[2*nf+1] = v1;
                ss = fmaf(v0, v0, fmaf(v1, v1, ss));
            }
            if (sect < 2) {
                ss += __shfl_xor_sync(0xffffffffu, ss, 1);
                ss += __shfl_xor_sync(0xffffffffu, ss, 2);
                float inv = 1.f / fmaxf(sqrtf(ss), 1e-12f);
                float* dst = (sect == 0 ? g_Q : g_K) + (((long)(b*H + hh) * LQ + ltok) << 5);
                #pragma unroll
                for (int nf = 0; nf < 4; nf++) {
                    int d = nf*8 + 2*(lane & 3);
                    float2 t = make_float2(v8[2*nf]*inv, v8[2*nf+1]*inv);
                    *(float2*)(dst + d) = t;
                }
            } else {
                float* dst = g_V + (((long)(b*H + hh) * LQ + ltok) << 5);
                #pragma unroll
                for (int nf = 0; nf < 4; nf++) {
                    int d = nf*8 + 2*(lane & 3);
                    float2 t = make_float2(v8[2*nf], v8[2*nf+1]);
                    *(float2*)(dst + d) = t;
                }
            }
        }
    }
}

// ---------------------------------------------------------------------------
// 4) Attention (tensor cores), REDUCED REGISTER TILE.
//    Block = quarter of a (b,h): 64 q-rows, 4 warps x 16 rows. grid = 2048*4.
//    Removes the mf dimension -> ~half the live registers; __launch_bounds__
//    (128,4) caps regs at 128 for 4 blocks/SM; carveout raised to fit 4x53.7KB.
// ---------------------------------------------------------------------------
#define ATTN_KSM_BYTES (256*36*4)             // 36864
#define ATTN_SMEM (ATTN_KSM_BYTES + 32*264*2) // 53760

__global__ void __launch_bounds__(128, 4) k_attn(const float* __restrict__ logit_scale)
{
    extern __shared__ char smraw[];
    float* Ksm = (float*)smraw;                         // [256][36] raw fp32
    __half* Vt = (__half*)(smraw + ATTN_KSM_BYTES);     // [32][264]

    const int bx = blockIdx.x;
    const int bh = bx >> 2;
    const int quarter = bx & 3;
    const int h = bh & 3;
    const long base = (long)bh * (LQ * HD);
    const int tid = threadIdx.x;
    const int lane = tid & 31;
    const int warp = tid >> 5;

    {
        const float4* Ks4 = (const float4*)(g_K + base);
        for (int i = tid; i < 2048; i += 128)
            *(float4*)(Ksm + (i >> 3) * 36 + ((i & 7) << 2)) = Ks4[i];
        const float* Vp = g_V + base;
        for (int i = tid; i < 8192; i += 128) {
            int key = i >> 5, d = i & 31;
            Vt[d*264 + key] = __float2half(Vp[i]);
        }
    }
    __syncthreads();

    const float scale = __expf(fminf(logit_scale[h], 4.6051702f));
    const int qrow0 = quarter * 64 + warp * 16;

    // Q frags: 3xtf32 hi/lo, single 16-row m-frag
    unsigned qh[4][4], ql[4][4];
    {
        const float* Qp = g_Q + base;
        int r = qrow0 + (lane >> 2);
        #pragma unroll
        for (int ks = 0; ks < 4; ks++) {
            int cc = ks*8 + (lane & 3);
            tf32split(Qp[r*32 + cc],        qh[ks][0], ql[ks][0]);
            tf32split(Qp[(r+8)*32 + cc],    qh[ks][1], ql[ks][1]);
            tf32split(Qp[r*32 + cc + 4],    qh[ks][2], ql[ks][2]);
            tf32split(Qp[(r+8)*32 + cc + 4],qh[ks][3], ql[ks][3]);
        }
    }

    float o[4][4];
    #pragma unroll
    for (int j = 0; j < 4; j++)
        #pragma unroll
        for (int r = 0; r < 4; r++) o[j][r] = 0.f;
    float rsum[2] = {0.f, 0.f};
    float M[2] = {-1e30f, -1e30f};

    const float* biasH = g_biasF + (h << 16);

    for (int tile = 0; tile < 4; tile++) {
        const int kt = tile * 64;
        float s[8][4];
        #pragma unroll
        for (int j = 0; j < 8; j++)
            #pragma unroll
            for (int r = 0; r < 4; r++) s[j][r] = 0.f;

        // S = Q K^T, 3xtf32
        #pragma unroll
        for (int ks = 0; ks < 4; ks++) {
            #pragma unroll
            for (int nf = 0; nf < 8; nf++) {
                int key = kt + nf*8 + (lane >> 2);
                int dd = ks*8 + (lane & 3);
                unsigned bh0, bl0, bh1, bl1;
                tf32split(Ksm[key*36 + dd],     bh0, bl0);
                tf32split(Ksm[key*36 + dd + 4], bh1, bl1);
                mma_tf32(s[nf], qh[ks], bh0, bh1);
                mma_tf32(s[nf], qh[ks], bl0, bl1);
                mma_tf32(s[nf], ql[ks], bh0, bh1);
            }
        }

        // logits = s*scale + bias; per-row tile max
        float tmax[2] = {-1e30f, -1e30f};
        {
            int r0 = qrow0 + (lane >> 2);
            #pragma unroll
            for (int nf = 0; nf < 8; nf++) {
                int k0 = kt + nf*8 + 2*(lane & 3);
                float2 bA = *(const float2*)(biasH + r0*256 + k0);
                float2 bB = *(const float2*)(biasH + (r0+8)*256 + k0);
                s[nf][0] = fmaf(s[nf][0], scale, bA.x);
                s[nf][1] = fmaf(s[nf][1], scale, bA.y);
                s[nf][2] = fmaf(s[nf][2], scale, bB.x);
                s[nf][3] = fmaf(s[nf][3], scale, bB.y);
                tmax[0] = fmaxf(tmax[0], fmaxf(s[nf][0], s[nf][1]));
                tmax[1] = fmaxf(tmax[1], fmaxf(s[nf][2], s[nf][3]));
            }
        }
        #pragma unroll
        for (int g = 0; g < 2; g++) {
            tmax[g] = fmaxf(tmax[g], __shfl_xor_sync(0xffffffffu, tmax[g], 1));
            tmax[g] = fmaxf(tmax[g], __shfl_xor_sync(0xffffffffu, tmax[g], 2));
        }
        float corr[2];
        #pragma unroll
        for (int g = 0; g < 2; g++) {
            float Mn = fmaxf(M[g], tmax[g]);
            corr[g] = __expf(M[g] - Mn);
            M[g] = Mn;
            rsum[g] *= corr[g];
        }
        #pragma unroll
        for (int nf2 = 0; nf2 < 4; nf2++) {
            o[nf2][0] *= corr[0];
            o[nf2][1] *= corr[0];
            o[nf2][2] *= corr[1];
            o[nf2][3] *= corr[1];
        }

        // p = exp(logit - M), pack fp16, accumulate rsum
        unsigned ph[8][2];
        #pragma unroll
        for (int nf = 0; nf < 8; nf++) {
            float p0 = __expf(s[nf][0] - M[0]);
            float p1 = __expf(s[nf][1] - M[0]);
            float p2 = __expf(s[nf][2] - M[1]);
            float p3 = __expf(s[nf][3] - M[1]);
            rsum[0] += p0 + p1;
            rsum[1] += p2 + p3;
            ph[nf][0] = packh2(p0, p1);
            ph[nf][1] = packh2(p2, p3);
        }

        // O += P V
        #pragma unroll
        for (int kk = 0; kk < 4; kk++) {
            int key0 = kt + kk*16 + 2*(lane & 3);
            #pragma unroll
            for (int nf2 = 0; nf2 < 4; nf2++) {
                int n = nf2*8 + (lane >> 2);
                unsigned vb0 = *(const unsigned*)(Vt + n*264 + key0);
                unsigned vb1 = *(const unsigned*)(Vt + n*264 + key0 + 8);
                mma_f16(o[nf2], ph[2*kk][0], ph[2*kk][1],
                        ph[2*kk+1][0], ph[2*kk+1][1], vb0, vb1);
            }
        }
    }

    // reduce row sums over quad lanes
    #pragma unroll
    for (int i = 0; i < 2; i++) {
        rsum[i] += __shfl_xor_sync(0xffffffffu, rsum[i], 1);
        rsum[i] += __shfl_xor_sync(0xffffffffu, rsum[i], 2);
        rsum[i] = 1.f / rsum[i];
    }

    const int b = bh >> 2;
    #pragma unroll
    for (int sub = 0; sub < 2; sub++) {
        int row = qrow0 + sub*8 + (lane >> 2);
        float inv = rsum[sub];
        float* dst = g_O + ((long)(b*LQ + row) * C) + h * HD;
        #pragma unroll
        for (int nf2 = 0; nf2 < 4; nf2++) {
            int d = nf2*8 + 2*(lane & 3);
            float2 t = make_float2(o[nf2][2*sub] * inv,
                                   o[nf2][2*sub+1] * inv);
            *(float2*)(dst + d) = t;
        }
    }
}

// ---------------------------------------------------------------------------
// 5) Output projection (single tf32 mma): out = O @ proj_w^T + proj_b
// ---------------------------------------------------------------------------
__global__ void __launch_bounds__(128) k_proj(const float* __restrict__ proj_w,
                                              const float* __restrict__ proj_b,
                                              float* __restrict__ out)
{
    extern __shared__ char smraw[];
    float* Xs = (float*)smraw;
    float* Ws = (float*)(smraw + 64*132*4);

    const int tid = threadIdx.x;
    const int lane = tid & 31;
    const int warp = tid >> 5;
    const int wm = (warp & 1) * 32;
    const int wn = (warp >> 1) * 32;
    const int mbase = blockIdx.x * 64;
    const int nbase = blockIdx.y * 64;

    {
        const float4* src = (const float4*)(g_O + (long)mbase * 128);
        for (int i = tid; i < 2048; i += 128) {
            float4 v = src[i];
            v.x = tf32r(v.x); v.y = tf32r(v.y); v.z = tf32r(v.z); v.w = tf32r(v.w);
            *(float4*)(Xs + (i >> 5) * 132 + ((i & 31) << 2)) = v;
        }
        const float4* wsrc = (const float4*)(proj_w + (long)nbase * 128);
        for (int i = tid; i < 2048; i += 128) {
            float4 v = wsrc[i];
            v.x = tf32r(v.x); v.y = tf32r(v.y); v.z = tf32r(v.z); v.w = tf32r(v.w);
            *(float4*)(Ws + (i >> 5) * 132 + ((i & 31) << 2)) = v;
        }
    }
    __syncthreads();

    float acc[2][4][4];
    #pragma unroll
    for (int i = 0; i < 2; i++)
        #pragma unroll
        for (int j = 0; j < 4; j++)
            #pragma unroll
            for (int r = 0; r < 4; r++) acc[i][j][r] = 0.f;

    #pragma unroll 4
    for (int ks = 0; ks < 16; ks++) {
        unsigned a[2][4];
        #pragma unroll
        for (int mf = 0; mf < 2; mf++) {
            int r = wm + mf*16 + (lane >> 2);
            int cc = ks*8 + (lane & 3);
            a[mf][0] = __float_as_uint(Xs[r*132 + cc]);
            a[mf][1] = __float_as_uint(Xs[(r+8)*132 + cc]);
            a[mf][2] = __float_as_uint(Xs[r*132 + cc + 4]);
            a[mf][3] = __float_as_uint(Xs[(r+8)*132 + cc + 4]);
        }
        #pragma unroll
        for (int nf = 0; nf < 4; nf++) {
            int n = wn + nf*8 + (lane >> 2);
            int cc = ks*8 + (lane & 3);
            unsigned b0 = __float_as_uint(Ws[n*132 + cc]);
            unsigned b1 = __float_as_uint(Ws[n*132 + cc + 4]);
            mma_tf32(acc[0][nf], a[0], b0, b1);
            mma_tf32(acc[1][nf], a[1], b0, b1);
        }
    }

    const int colg0 = nbase + wn;
    float pb[4][2];
    #pragma unroll
    for (int nf = 0; nf < 4; nf++) {
        int cg = colg0 + nf*8 + 2*(lane & 3);
        pb[nf][0] = proj_b[cg];
        pb[nf][1] = proj_b[cg+1];
    }

    #pragma unroll
    for (int mf = 0; mf < 2; mf++) {
        #pragma unroll
        for (int sub = 0; sub < 2; sub++) {
            int m = mbase + wm + mf*16 + sub*8 + (lane >> 2);
            #pragma unroll
            for (int nf = 0; nf < 4; nf++) {
                int cg = colg0 + nf*8 + 2*(lane & 3);
                float2 t = make_float2(acc[mf][nf][2*sub]   + pb[nf][0],
                                       acc[mf][nf][2*sub+1] + pb[nf][1]);
                *(float2*)(out + (long)m * 128 + cg) = t;
            }
        }
    }
}

// ---------------------------------------------------------------------------
extern "C" void kernel_launch(void* const* d_in, const int* in_sizes, int n_in,
                              void* d_out, int out_size)
{
    const float* x           = (const float*)d_in[0];
    const float* qkv_w       = (const float*)d_in[1];
    const float* q_bias      = (const float*)d_in[2];
    const float* v_bias      = (const float*)d_in[3];
    const float* logit_scale = (const float*)d_in[4];
    const float* cpb_w1      = (const float*)d_in[5];
    const float* cpb_b1      = (const float*)d_in[6];
    const float* cpb_w2      = (const float*)d_in[7];
    const float* proj_w      = (const float*)d_in[8];
    const float* proj_b      = (const float*)d_in[9];
    const float* rel_table   = (const float*)d_in[10];
    const int*   rel_index   = (const int*)d_in[11];
    float* out = (float*)d_out;

    cudaFuncSetAttribute(k_qkv,  cudaFuncAttributeMaxDynamicSharedMemorySize, GEMM_SMEM);
    cudaFuncSetAttribute(k_proj, cudaFuncAttributeMaxDynamicSharedMemorySize, GEMM_SMEM);
    cudaFuncSetAttribute(k_attn, cudaFuncAttributeMaxDynamicSharedMemorySize, ATTN_SMEM);
    cudaFuncSetAttribute(k_attn, cudaFuncAttributePreferredSharedMemoryCarveout, 100);

    k_cpb<<<M_TAB, 128>>>(rel_table, cpb_w1, cpb_b1, cpb_w2);
    k_expand<<<(H*LQ*LQ) / 256, 256>>>(rel_index);
    k_qkv<<<dim3(ROWS_TOT/64, 6), 128, GEMM_SMEM>>>(x, qkv_w, q_bias, v_bias);
    k_attn<<<BW * H * 4, 128, ATTN_SMEM>>>(logit_scale);
    k_proj<<<dim3(ROWS_TOT/64, 2), 128, GEMM_SMEM>>>(proj_w, proj_b, out);
}